// round 1
// baseline (speedup 1.0000x reference)
#include <cuda_runtime.h>
#include <math.h>

#define B   2
#define T   1024
#define H   2048
#define NH  32
#define NKV 8
#define HD  64
#define IM  8192
#define M   (B*T)

// ---------------- scratch (device globals; no allocation) ----------------
__device__ __align__(16) float g_xn  [M * H];
__device__ __align__(16) float g_q   [M * NH * HD];
__device__ __align__(16) float g_k   [M * NKV * HD];
__device__ __align__(16) float g_v   [M * NKV * HD];
__device__ __align__(16) float g_attn[M * NH * HD];
__device__ __align__(16) float g_h2  [M * H];
__device__ __align__(16) float g_xn2 [M * H];
__device__ __align__(16) float g_g   [(size_t)M * IM];
__device__ __align__(16) float g_u   [(size_t)M * IM];

// ---------------- RMSNorm ----------------
__global__ void rmsnorm_kernel(const float* __restrict__ x,
                               const float* __restrict__ w,
                               float* __restrict__ out) {
    int row = blockIdx.x;
    const float* xr = x + (size_t)row * H;
    float ss = 0.f;
    for (int i = threadIdx.x; i < H / 4; i += blockDim.x) {
        float4 v = ((const float4*)xr)[i];
        ss += v.x * v.x + v.y * v.y + v.z * v.z + v.w * v.w;
    }
    __shared__ float red[32];
    #pragma unroll
    for (int o = 16; o; o >>= 1) ss += __shfl_xor_sync(0xffffffffu, ss, o);
    if ((threadIdx.x & 31) == 0) red[threadIdx.x >> 5] = ss;
    __syncthreads();
    if (threadIdx.x < 32) {
        float v = (threadIdx.x < (blockDim.x >> 5)) ? red[threadIdx.x] : 0.f;
        #pragma unroll
        for (int o = 16; o; o >>= 1) v += __shfl_xor_sync(0xffffffffu, v, o);
        if (threadIdx.x == 0) red[0] = v;
    }
    __syncthreads();
    float r = rsqrtf(red[0] / (float)H + 1e-6f);
    float* orow = out + (size_t)row * H;
    for (int i = threadIdx.x; i < H / 4; i += blockDim.x) {
        float4 v = ((const float4*)xr)[i];
        float4 wv = ((const float4*)w)[i];
        float4 o4 = make_float4(v.x * r * wv.x, v.y * r * wv.y,
                                v.z * r * wv.z, v.w * r * wv.w);
        ((float4*)orow)[i] = o4;
    }
}

// ---------------- GEMM: C[m,n] = sum_k A[m,k]*Bm[n,k] (+res) ----------------
// A: (Mm,K) row-major, Bm: (N,K) row-major. Mm,N % 128 == 0, K % 16 == 0.
__global__ void __launch_bounds__(256)
gemm_nt_kernel(const float* __restrict__ A, const float* __restrict__ Bm,
               const float* __restrict__ res, float* __restrict__ C,
               int N, int K) {
    __shared__ __align__(16) float As[16][128];
    __shared__ __align__(16) float Bs[16][128];

    const int bm = blockIdx.y * 128;
    const int bn = blockIdx.x * 128;
    const int tid = threadIdx.x;
    const int tx = tid & 15, ty = tid >> 4;
    const int lrow = tid >> 2;
    const int lcol = (tid & 3) << 2;

    const float* Ap  = A  + (size_t)(bm + lrow)      * K + lcol;
    const float* Ap2 = A  + (size_t)(bm + lrow + 64) * K + lcol;
    const float* Bp  = Bm + (size_t)(bn + lrow)      * K + lcol;
    const float* Bp2 = Bm + (size_t)(bn + lrow + 64) * K + lcol;

    float acc[8][8] = {};

    for (int k0 = 0; k0 < K; k0 += 16) {
        float4 a0 = *(const float4*)(Ap  + k0);
        float4 a1 = *(const float4*)(Ap2 + k0);
        float4 b0 = *(const float4*)(Bp  + k0);
        float4 b1 = *(const float4*)(Bp2 + k0);
        As[lcol + 0][lrow]      = a0.x; As[lcol + 1][lrow]      = a0.y;
        As[lcol + 2][lrow]      = a0.z; As[lcol + 3][lrow]      = a0.w;
        As[lcol + 0][lrow + 64] = a1.x; As[lcol + 1][lrow + 64] = a1.y;
        As[lcol + 2][lrow + 64] = a1.z; As[lcol + 3][lrow + 64] = a1.w;
        Bs[lcol + 0][lrow]      = b0.x; Bs[lcol + 1][lrow]      = b0.y;
        Bs[lcol + 2][lrow]      = b0.z; Bs[lcol + 3][lrow]      = b0.w;
        Bs[lcol + 0][lrow + 64] = b1.x; Bs[lcol + 1][lrow + 64] = b1.y;
        Bs[lcol + 2][lrow + 64] = b1.z; Bs[lcol + 3][lrow + 64] = b1.w;
        __syncthreads();

        #pragma unroll
        for (int k = 0; k < 16; k++) {
            float4 a04 = *(const float4*)&As[k][ty * 4];
            float4 a14 = *(const float4*)&As[k][ty * 4 + 64];
            float4 b04 = *(const float4*)&Bs[k][tx * 4];
            float4 b14 = *(const float4*)&Bs[k][tx * 4 + 64];
            float a[8] = {a04.x, a04.y, a04.z, a04.w, a14.x, a14.y, a14.z, a14.w};
            float b[8] = {b04.x, b04.y, b04.z, b04.w, b14.x, b14.y, b14.z, b14.w};
            #pragma unroll
            for (int i = 0; i < 8; i++)
                #pragma unroll
                for (int j = 0; j < 8; j++)
                    acc[i][j] = fmaf(a[i], b[j], acc[i][j]);
        }
        __syncthreads();
    }

    #pragma unroll
    for (int i = 0; i < 8; i++) {
        int m = bm + ((i < 4) ? ty * 4 + i : 64 + ty * 4 + (i - 4));
        #pragma unroll
        for (int jh = 0; jh < 2; jh++) {
            int n = bn + jh * 64 + tx * 4;
            float4 v = make_float4(acc[i][jh * 4 + 0], acc[i][jh * 4 + 1],
                                   acc[i][jh * 4 + 2], acc[i][jh * 4 + 3]);
            if (res) {
                float4 rv = *(const float4*)(res + (size_t)m * N + n);
                v.x += rv.x; v.y += rv.y; v.z += rv.z; v.w += rv.w;
            }
            *(float4*)(C + (size_t)m * N + n) = v;
        }
    }
}

// ---------------- RoPE ----------------
__global__ void rope_q_kernel(float* __restrict__ q,
                              const float* __restrict__ cosp,
                              const float* __restrict__ sinp,
                              const int* __restrict__ pos) {
    int idx = blockIdx.x * blockDim.x + threadIdx.x;   // B*T*NH*32
    int d2 = idx & 31;
    int h  = (idx >> 5) & (NH - 1);
    int bt = idx >> 10;                                // b*T + t
    int p  = pos[bt];
    float c = cosp[p * 32 + d2], s = sinp[p * 32 + d2];
    size_t base = (size_t)bt * (NH * HD) + h * HD + 2 * d2;
    float x1 = q[base], x2 = q[base + 1];
    q[base]     = x1 * c - x2 * s;
    q[base + 1] = x1 * s + x2 * c;
}

__global__ void rope_kv_kernel(float* __restrict__ k, const float* __restrict__ v,
                               const float* __restrict__ cosp,
                               const float* __restrict__ sinp,
                               const int* __restrict__ pos,
                               float* __restrict__ outk, float* __restrict__ outv) {
    int idx = blockIdx.x * blockDim.x + threadIdx.x;   // B*T*NKV*32
    int d2 = idx & 31;
    int h  = (idx >> 5) & (NKV - 1);
    int bt = idx >> 8;                                 // b*T + t
    int t  = bt & (T - 1);
    int b  = bt >> 10;
    int p  = pos[bt];
    float c = cosp[p * 32 + d2], s = sinp[p * 32 + d2];
    size_t base = (size_t)bt * (NKV * HD) + h * HD + 2 * d2;
    float x1 = k[base], x2 = k[base + 1];
    float r1 = x1 * c - x2 * s;
    float r2 = x1 * s + x2 * c;
    k[base] = r1; k[base + 1] = r2;
    size_t ob = (((size_t)(b * NKV + h)) * T + t) * HD + 2 * d2;
    outk[ob] = r1;       outk[ob + 1] = r2;
    outv[ob] = v[base];  outv[ob + 1] = v[base + 1];
}

// ---------------- Flash attention (64x64 tiles, fp32) ----------------
__global__ void __launch_bounds__(256)
attn_kernel(const float* __restrict__ Q, const float* __restrict__ Kg,
            const float* __restrict__ Vg, float* __restrict__ O) {
    __shared__ __align__(16) float QsT[64][64];   // [d][m]
    __shared__ __align__(16) float KsT[64][64];   // [d][n], reused as Ps[m][n]
    __shared__ __align__(16) float Vs [64][64];   // [n][d]
    float (*Ps)[64] = KsT;

    const int qt = blockIdx.x, h = blockIdx.y, b = blockIdx.z;
    const int kvh = h >> 2;                       // NH/NKV = 4
    const int tid = threadIdx.x;
    const int rg = tid >> 4, cg = tid & 15;
    const int m0 = rg * 4, n0 = cg * 4;

    {   // load Q tile (transposed into smem)
        const int m = tid >> 2;
        const int d0 = (tid & 3) * 16;
        const float* qp = Q + ((size_t)(b * T + qt * 64 + m)) * (NH * HD) + h * HD + d0;
        #pragma unroll
        for (int i = 0; i < 16; i++) QsT[d0 + i][m] = qp[i];
    }

    float o_acc[4][4] = {};
    float row_max[4] = {-1e30f, -1e30f, -1e30f, -1e30f};
    float row_sum[4] = {0.f, 0.f, 0.f, 0.f};

    for (int kt = 0; kt <= qt; kt++) {
        __syncthreads();   // prev-iter Ps/Vs reads done before overwrite
        {
            const int n = tid >> 2;
            const int d0 = (tid & 3) * 16;
            const float* kp = Kg + ((size_t)(b * T + kt * 64 + n)) * (NKV * HD) + kvh * HD + d0;
            const float* vp = Vg + ((size_t)(b * T + kt * 64 + n)) * (NKV * HD) + kvh * HD + d0;
            #pragma unroll
            for (int i = 0; i < 16; i++) KsT[d0 + i][n] = kp[i];
            #pragma unroll
            for (int i = 0; i < 16; i += 4)
                *(float4*)&Vs[n][d0 + i] = *(const float4*)(vp + i);
        }
        __syncthreads();

        float s[4][4] = {};
        #pragma unroll 16
        for (int d = 0; d < 64; d++) {
            float4 av = *(const float4*)&QsT[d][m0];
            float4 bv = *(const float4*)&KsT[d][n0];
            float aa[4] = {av.x, av.y, av.z, av.w};
            float bb[4] = {bv.x, bv.y, bv.z, bv.w};
            #pragma unroll
            for (int i = 0; i < 4; i++)
                #pragma unroll
                for (int j = 0; j < 4; j++)
                    s[i][j] = fmaf(aa[i], bb[j], s[i][j]);
        }

        const float scale = 0.125f;   // 1/sqrt(64)
        if (kt == qt) {
            #pragma unroll
            for (int i = 0; i < 4; i++)
                #pragma unroll
                for (int j = 0; j < 4; j++)
                    s[i][j] = (n0 + j <= m0 + i) ? s[i][j] * scale : -1e30f;
        } else {
            #pragma unroll
            for (int i = 0; i < 4; i++)
                #pragma unroll
                for (int j = 0; j < 4; j++)
                    s[i][j] *= scale;
        }

        float p[4][4];
        #pragma unroll
        for (int i = 0; i < 4; i++) {
            float mx = fmaxf(fmaxf(s[i][0], s[i][1]), fmaxf(s[i][2], s[i][3]));
            #pragma unroll
            for (int o = 1; o < 16; o <<= 1)
                mx = fmaxf(mx, __shfl_xor_sync(0xffffffffu, mx, o));
            float nm = fmaxf(row_max[i], mx);
            float alpha = __expf(row_max[i] - nm);
            row_max[i] = nm;
            float rs = 0.f;
            #pragma unroll
            for (int j = 0; j < 4; j++) { p[i][j] = __expf(s[i][j] - nm); rs += p[i][j]; }
            #pragma unroll
            for (int o = 1; o < 16; o <<= 1)
                rs += __shfl_xor_sync(0xffffffffu, rs, o);
            row_sum[i] = row_sum[i] * alpha + rs;
            #pragma unroll
            for (int j = 0; j < 4; j++) o_acc[i][j] *= alpha;
        }

        __syncthreads();   // all KsT reads done; safe to overwrite with Ps
        #pragma unroll
        for (int i = 0; i < 4; i++)
            #pragma unroll
            for (int j = 0; j < 4; j++)
                Ps[m0 + i][n0 + j] = p[i][j];
        __syncthreads();

        #pragma unroll 8
        for (int n = 0; n < 64; n++) {
            float4 vv = *(const float4*)&Vs[n][n0];
            float vb[4] = {vv.x, vv.y, vv.z, vv.w};
            #pragma unroll
            for (int i = 0; i < 4; i++) {
                float pv = Ps[m0 + i][n];
                #pragma unroll
                for (int j = 0; j < 4; j++)
                    o_acc[i][j] = fmaf(pv, vb[j], o_acc[i][j]);
            }
        }
    }

    #pragma unroll
    for (int i = 0; i < 4; i++) {
        float inv = 1.f / row_sum[i];
        int t = qt * 64 + m0 + i;
        float4 ov = make_float4(o_acc[i][0] * inv, o_acc[i][1] * inv,
                                o_acc[i][2] * inv, o_acc[i][3] * inv);
        *(float4*)(O + ((size_t)(b * T + t)) * (NH * HD) + h * HD + n0) = ov;
    }
}

// ---------------- SwiGLU elementwise ----------------
__global__ void silu_mul_kernel(float* __restrict__ g, const float* __restrict__ u) {
    int i = blockIdx.x * blockDim.x + threadIdx.x;   // over n/4
    float4 gv = ((const float4*)g)[i];
    float4 uv = ((const float4*)u)[i];
    gv.x = gv.x / (1.f + __expf(-gv.x)) * uv.x;
    gv.y = gv.y / (1.f + __expf(-gv.y)) * uv.y;
    gv.z = gv.z / (1.f + __expf(-gv.z)) * uv.z;
    gv.w = gv.w / (1.f + __expf(-gv.w)) * uv.w;
    ((float4*)g)[i] = gv;
}

// ---------------- launch ----------------
extern "C" void kernel_launch(void* const* d_in, const int* in_sizes, int n_in,
                              void* d_out, int out_size) {
    const float* hs   = (const float*)d_in[0];
    const float* cosp = (const float*)d_in[1];
    const float* sinp = (const float*)d_in[2];
    const int*   pos  = (const int*)  d_in[3];
    // d_in[4] = attention_mask (pure causal; implemented analytically)
    const float* n1w  = (const float*)d_in[5];
    const float* wq   = (const float*)d_in[6];
    const float* wk   = (const float*)d_in[7];
    const float* wv   = (const float*)d_in[8];
    const float* wo   = (const float*)d_in[9];
    const float* n2w  = (const float*)d_in[10];
    const float* wg   = (const float*)d_in[11];
    const float* wu   = (const float*)d_in[12];
    const float* wd   = (const float*)d_in[13];

    float *xn, *q, *k, *v, *attn, *h2, *xn2, *gg, *uu;
    cudaGetSymbolAddress((void**)&xn,   g_xn);
    cudaGetSymbolAddress((void**)&q,    g_q);
    cudaGetSymbolAddress((void**)&k,    g_k);
    cudaGetSymbolAddress((void**)&v,    g_v);
    cudaGetSymbolAddress((void**)&attn, g_attn);
    cudaGetSymbolAddress((void**)&h2,   g_h2);
    cudaGetSymbolAddress((void**)&xn2,  g_xn2);
    cudaGetSymbolAddress((void**)&gg,   g_g);
    cudaGetSymbolAddress((void**)&uu,   g_u);

    float* out_x = (float*)d_out;
    float* out_k = out_x + (size_t)M * H;
    float* out_v = out_k + (size_t)B * NKV * T * HD;

    // 1. RMSNorm 1
    rmsnorm_kernel<<<M, 256>>>(hs, n1w, xn);
    // 2. Q/K/V projections (NT GEMMs)
    gemm_nt_kernel<<<dim3(16, 16), 256>>>(xn, wq, nullptr, q, NH * HD, H);
    gemm_nt_kernel<<<dim3( 4, 16), 256>>>(xn, wk, nullptr, k, NKV * HD, H);
    gemm_nt_kernel<<<dim3( 4, 16), 256>>>(xn, wv, nullptr, v, NKV * HD, H);
    // 3. RoPE + KV-cache writeout
    rope_q_kernel <<<(B * T * NH  * (HD / 2)) / 256, 256>>>(q, cosp, sinp, pos);
    rope_kv_kernel<<<(B * T * NKV * (HD / 2)) / 256, 256>>>(k, v, cosp, sinp, pos,
                                                            out_k, out_v);
    // 4. Attention
    attn_kernel<<<dim3(T / 64, NH, B), 256>>>(q, k, v, attn);
    // 5. O-projection + residual
    gemm_nt_kernel<<<dim3(16, 16), 256>>>(attn, wo, hs, h2, H, NH * HD);
    // 6. RMSNorm 2
    rmsnorm_kernel<<<M, 256>>>(h2, n2w, xn2);
    // 7. MLP gate/up
    gemm_nt_kernel<<<dim3(64, 16), 256>>>(xn2, wg, nullptr, gg, IM, H);
    gemm_nt_kernel<<<dim3(64, 16), 256>>>(xn2, wu, nullptr, uu, IM, H);
    // 8. SwiGLU
    silu_mul_kernel<<<((size_t)M * IM / 4) / 256, 256>>>(gg, uu);
    // 9. Down projection + residual -> x output
    gemm_nt_kernel<<<dim3(16, 16), 256>>>(gg, wd, h2, out_x, H, IM);
}

// round 4
// speedup vs baseline: 1.8708x; 1.8708x over previous
#include <cuda_runtime.h>
#include <math.h>
#include <stdint.h>

#define B   2
#define T   1024
#define H   2048
#define NH  32
#define NKV 8
#define HD  64
#define IM  8192
#define M   (B*T)

// ---------------- scratch (device globals; no allocation) ----------------
__device__ __align__(16) float g_xn  [M * H];
__device__ __align__(16) float g_q   [M * NH * HD];
__device__ __align__(16) float g_k   [M * NKV * HD];
__device__ __align__(16) float g_v   [M * NKV * HD];
__device__ __align__(16) float g_attn[M * NH * HD];
__device__ __align__(16) float g_h2  [M * H];
__device__ __align__(16) float g_xn2 [M * H];
__device__ __align__(16) float g_g   [(size_t)M * IM];
__device__ __align__(16) float g_u   [(size_t)M * IM];

// ---------------- helpers ----------------
__device__ __forceinline__ uint32_t smem_u32(const void* p) {
    uint32_t a;
    asm("{ .reg .u64 t; cvta.to.shared.u64 t, %1; cvt.u32.u64 %0, t; }"
        : "=r"(a) : "l"(p));
    return a;
}

__device__ __forceinline__ void cp_async16(uint32_t dst, const void* src) {
    asm volatile("cp.async.cg.shared.global [%0], [%1], 16;"
                 :: "r"(dst), "l"(src));
}
#define CP_ASYNC_COMMIT() asm volatile("cp.async.commit_group;" ::: "memory")
#define CP_ASYNC_WAIT0()  asm volatile("cp.async.wait_group 0;" ::: "memory")

__device__ __forceinline__ void mma_tf32(float& c0, float& c1, float& c2, float& c3,
                                         uint32_t a0, uint32_t a1, uint32_t a2, uint32_t a3,
                                         uint32_t b0, uint32_t b1) {
    asm volatile(
        "mma.sync.aligned.m16n8k8.row.col.f32.tf32.tf32.f32 "
        "{%0,%1,%2,%3}, {%4,%5,%6,%7}, {%8,%9}, {%0,%1,%2,%3};"
        : "+f"(c0), "+f"(c1), "+f"(c2), "+f"(c3)
        : "r"(a0), "r"(a1), "r"(a2), "r"(a3), "r"(b0), "r"(b1));
}

// round-to-nearest tf32 high part; lo = x - hi
__device__ __forceinline__ uint32_t tf32_rna(float x) {
    uint32_t r;
    asm("cvt.rna.tf32.f32 %0, %1;" : "=r"(r) : "f"(x));
    return r;
}

// ---------------- 3xTF32 mma.sync GEMM: C[m,n] = sum_k A[m,k]*Bm[n,k] (+res) --
// A: (Mtot,K) row-major fp32; Bm: (N,K) row-major fp32. M,N %128==0, K %32==0.
// CTA tile 128x128, K chunk 32, double-buffered cp.async.
// Precision: hi/lo split, acc += a_hi*b_hi + a_hi*b_lo + a_lo*b_hi.
#define GPAD 36                                   // floats per smem row (32+4)
#define A_BUF_FLOATS (128 * GPAD)                 // 4608
#define GEMM_DSMEM   (4 * A_BUF_FLOATS * 4)       // A0,B0,A1,B1 = 73728 B

__global__ void __launch_bounds__(256, 1)
gemm_mma_kernel(const float* __restrict__ A, const float* __restrict__ Bm,
                const float* __restrict__ res, float* __restrict__ C,
                int N, int K) {
    extern __shared__ float sm[];
    float* As[2] = { sm,                    sm + 2 * A_BUF_FLOATS };
    float* Bs[2] = { sm + A_BUF_FLOATS,     sm + 3 * A_BUF_FLOATS };
    const uint32_t smem_base = smem_u32(sm);

    const int tid  = threadIdx.x;
    const int wid  = tid >> 5;
    const int lane = tid & 31;
    const int mw   = wid >> 1;            // 0..3 -> 32-row band
    const int nw   = wid & 1;             // 0..1 -> 64-col band
    const int gid  = lane >> 2;           // group id 0..7
    const int tig  = lane & 3;            // thread in group 0..3

    const int bm = blockIdx.y * 128;
    const int bn = blockIdx.x * 128;
    const int KC = K >> 5;                // chunks of 32

    const int lrow = tid >> 3;            // 0..31
    const int lc4  = tid & 7;             // float4 column 0..7

    float acc[2][8][4];
    #pragma unroll
    for (int i = 0; i < 2; i++)
        #pragma unroll
        for (int j = 0; j < 8; j++)
            #pragma unroll
            for (int l = 0; l < 4; l++) acc[i][j][l] = 0.f;

    auto issue_load = [&](int c, int buf) {
        const int k0 = c << 5;
        uint32_t abase = smem_base + (buf ? 2 * A_BUF_FLOATS * 4 : 0);
        uint32_t bbase = abase + A_BUF_FLOATS * 4;
        #pragma unroll
        for (int it = 0; it < 4; it++) {
            int row = it * 32 + lrow;
            cp_async16(abase + (row * GPAD + lc4 * 4) * 4,
                       A + (size_t)(bm + row) * K + k0 + lc4 * 4);
        }
        #pragma unroll
        for (int it = 0; it < 4; it++) {
            int row = it * 32 + lrow;
            cp_async16(bbase + (row * GPAD + lc4 * 4) * 4,
                       Bm + (size_t)(bn + row) * K + k0 + lc4 * 4);
        }
        CP_ASYNC_COMMIT();
    };

    issue_load(0, 0);

    for (int c = 0; c < KC; c++) {
        const int buf = c & 1;
        CP_ASYNC_WAIT0();
        __syncthreads();
        if (c + 1 < KC) issue_load(c + 1, buf ^ 1);

        const float* a_s = As[buf];
        const float* b_s = Bs[buf];

        #pragma unroll
        for (int ks = 0; ks < 4; ks++) {
            const int k0 = ks * 8;
            // A fragments: hi/lo split
            uint32_t ah[2][4], al[2][4];
            #pragma unroll
            for (int mt = 0; mt < 2; mt++) {
                int r0 = mw * 32 + mt * 16 + gid;
                float x0 = a_s[r0 * GPAD + k0 + tig];
                float x1 = a_s[(r0 + 8) * GPAD + k0 + tig];
                float x2 = a_s[r0 * GPAD + k0 + tig + 4];
                float x3 = a_s[(r0 + 8) * GPAD + k0 + tig + 4];
                ah[mt][0] = tf32_rna(x0); al[mt][0] = tf32_rna(x0 - __uint_as_float(ah[mt][0]));
                ah[mt][1] = tf32_rna(x1); al[mt][1] = tf32_rna(x1 - __uint_as_float(ah[mt][1]));
                ah[mt][2] = tf32_rna(x2); al[mt][2] = tf32_rna(x2 - __uint_as_float(ah[mt][2]));
                ah[mt][3] = tf32_rna(x3); al[mt][3] = tf32_rna(x3 - __uint_as_float(ah[mt][3]));
            }
            // B fragments: hi/lo split
            uint32_t bh[8][2], bl[8][2];
            #pragma unroll
            for (int nt = 0; nt < 8; nt++) {
                int nr = nw * 64 + nt * 8 + gid;
                float y0 = b_s[nr * GPAD + k0 + tig];
                float y1 = b_s[nr * GPAD + k0 + tig + 4];
                bh[nt][0] = tf32_rna(y0); bl[nt][0] = tf32_rna(y0 - __uint_as_float(bh[nt][0]));
                bh[nt][1] = tf32_rna(y1); bl[nt][1] = tf32_rna(y1 - __uint_as_float(bh[nt][1]));
            }
            #pragma unroll
            for (int mt = 0; mt < 2; mt++)
                #pragma unroll
                for (int nt = 0; nt < 8; nt++) {
                    // lo terms first, hi last (hi dominates, keeps acc well-conditioned)
                    mma_tf32(acc[mt][nt][0], acc[mt][nt][1],
                             acc[mt][nt][2], acc[mt][nt][3],
                             ah[mt][0], ah[mt][1], ah[mt][2], ah[mt][3],
                             bl[nt][0], bl[nt][1]);
                    mma_tf32(acc[mt][nt][0], acc[mt][nt][1],
                             acc[mt][nt][2], acc[mt][nt][3],
                             al[mt][0], al[mt][1], al[mt][2], al[mt][3],
                             bh[nt][0], bh[nt][1]);
                    mma_tf32(acc[mt][nt][0], acc[mt][nt][1],
                             acc[mt][nt][2], acc[mt][nt][3],
                             ah[mt][0], ah[mt][1], ah[mt][2], ah[mt][3],
                             bh[nt][0], bh[nt][1]);
                }
        }
        __syncthreads();
    }

    // ---- epilogue ----
    #pragma unroll
    for (int mt = 0; mt < 2; mt++) {
        int r0 = bm + mw * 32 + mt * 16 + gid;
        #pragma unroll
        for (int nt = 0; nt < 8; nt++) {
            int col = bn + nw * 64 + nt * 8 + tig * 2;
            size_t o0 = (size_t)r0 * N + col;
            size_t o1 = (size_t)(r0 + 8) * N + col;
            float2 v0 = make_float2(acc[mt][nt][0], acc[mt][nt][1]);
            float2 v1 = make_float2(acc[mt][nt][2], acc[mt][nt][3]);
            if (res) {
                float2 r0v = *(const float2*)(res + o0);
                float2 r1v = *(const float2*)(res + o1);
                v0.x += r0v.x; v0.y += r0v.y;
                v1.x += r1v.x; v1.y += r1v.y;
            }
            *(float2*)(C + o0) = v0;
            *(float2*)(C + o1) = v1;
        }
    }
}

// ---------------- RMSNorm ----------------
__global__ void rmsnorm_kernel(const float* __restrict__ x,
                               const float* __restrict__ w,
                               float* __restrict__ out) {
    int row = blockIdx.x;
    const float* xr = x + (size_t)row * H;
    float ss = 0.f;
    for (int i = threadIdx.x; i < H / 4; i += blockDim.x) {
        float4 v = ((const float4*)xr)[i];
        ss += v.x * v.x + v.y * v.y + v.z * v.z + v.w * v.w;
    }
    __shared__ float red[32];
    #pragma unroll
    for (int o = 16; o; o >>= 1) ss += __shfl_xor_sync(0xffffffffu, ss, o);
    if ((threadIdx.x & 31) == 0) red[threadIdx.x >> 5] = ss;
    __syncthreads();
    if (threadIdx.x < 32) {
        float v = (threadIdx.x < (blockDim.x >> 5)) ? red[threadIdx.x] : 0.f;
        #pragma unroll
        for (int o = 16; o; o >>= 1) v += __shfl_xor_sync(0xffffffffu, v, o);
        if (threadIdx.x == 0) red[0] = v;
    }
    __syncthreads();
    float r = rsqrtf(red[0] / (float)H + 1e-6f);
    float* orow = out + (size_t)row * H;
    for (int i = threadIdx.x; i < H / 4; i += blockDim.x) {
        float4 v = ((const float4*)xr)[i];
        float4 wv = ((const float4*)w)[i];
        float4 o4 = make_float4(v.x * r * wv.x, v.y * r * wv.y,
                                v.z * r * wv.z, v.w * r * wv.w);
        ((float4*)orow)[i] = o4;
    }
}

// ---------------- RoPE ----------------
__global__ void rope_q_kernel(float* __restrict__ q,
                              const float* __restrict__ cosp,
                              const float* __restrict__ sinp,
                              const int* __restrict__ pos) {
    int idx = blockIdx.x * blockDim.x + threadIdx.x;   // B*T*NH*32
    int d2 = idx & 31;
    int h  = (idx >> 5) & (NH - 1);
    int bt = idx >> 10;
    int p  = pos[bt];
    float c = cosp[p * 32 + d2], s = sinp[p * 32 + d2];
    size_t base = (size_t)bt * (NH * HD) + h * HD + 2 * d2;
    float x1 = q[base], x2 = q[base + 1];
    q[base]     = x1 * c - x2 * s;
    q[base + 1] = x1 * s + x2 * c;
}

__global__ void rope_kv_kernel(float* __restrict__ k, const float* __restrict__ v,
                               const float* __restrict__ cosp,
                               const float* __restrict__ sinp,
                               const int* __restrict__ pos,
                               float* __restrict__ outk, float* __restrict__ outv) {
    int idx = blockIdx.x * blockDim.x + threadIdx.x;   // B*T*NKV*32
    int d2 = idx & 31;
    int h  = (idx >> 5) & (NKV - 1);
    int bt = idx >> 8;
    int t  = bt & (T - 1);
    int b  = bt >> 10;
    int p  = pos[bt];
    float c = cosp[p * 32 + d2], s = sinp[p * 32 + d2];
    size_t base = (size_t)bt * (NKV * HD) + h * HD + 2 * d2;
    float x1 = k[base], x2 = k[base + 1];
    float r1 = x1 * c - x2 * s;
    float r2 = x1 * s + x2 * c;
    k[base] = r1; k[base + 1] = r2;
    size_t ob = (((size_t)(b * NKV + h)) * T + t) * HD + 2 * d2;
    outk[ob] = r1;       outk[ob + 1] = r2;
    outv[ob] = v[base];  outv[ob + 1] = v[base + 1];
}

// ---------------- Flash attention (64x64 tiles, fp32) ----------------
__global__ void __launch_bounds__(256)
attn_kernel(const float* __restrict__ Q, const float* __restrict__ Kg,
            const float* __restrict__ Vg, float* __restrict__ O) {
    __shared__ __align__(16) float QsT[64][64];
    __shared__ __align__(16) float KsT[64][64];
    __shared__ __align__(16) float Vs [64][64];
    float (*Ps)[64] = KsT;

    const int qt = blockIdx.x, h = blockIdx.y, b = blockIdx.z;
    const int kvh = h >> 2;
    const int tid = threadIdx.x;
    const int rg = tid >> 4, cg = tid & 15;
    const int m0 = rg * 4, n0 = cg * 4;

    {
        const int m = tid >> 2;
        const int d0 = (tid & 3) * 16;
        const float* qp = Q + ((size_t)(b * T + qt * 64 + m)) * (NH * HD) + h * HD + d0;
        #pragma unroll
        for (int i = 0; i < 16; i++) QsT[d0 + i][m] = qp[i];
    }

    float o_acc[4][4] = {};
    float row_max[4] = {-1e30f, -1e30f, -1e30f, -1e30f};
    float row_sum[4] = {0.f, 0.f, 0.f, 0.f};

    for (int kt = 0; kt <= qt; kt++) {
        __syncthreads();
        {
            const int n = tid >> 2;
            const int d0 = (tid & 3) * 16;
            const float* kp = Kg + ((size_t)(b * T + kt * 64 + n)) * (NKV * HD) + kvh * HD + d0;
            const float* vp = Vg + ((size_t)(b * T + kt * 64 + n)) * (NKV * HD) + kvh * HD + d0;
            #pragma unroll
            for (int i = 0; i < 16; i++) KsT[d0 + i][n] = kp[i];
            #pragma unroll
            for (int i = 0; i < 16; i += 4)
                *(float4*)&Vs[n][d0 + i] = *(const float4*)(vp + i);
        }
        __syncthreads();

        float s[4][4] = {};
        #pragma unroll 16
        for (int d = 0; d < 64; d++) {
            float4 av = *(const float4*)&QsT[d][m0];
            float4 bv = *(const float4*)&KsT[d][n0];
            float aa[4] = {av.x, av.y, av.z, av.w};
            float bb[4] = {bv.x, bv.y, bv.z, bv.w};
            #pragma unroll
            for (int i = 0; i < 4; i++)
                #pragma unroll
                for (int j = 0; j < 4; j++)
                    s[i][j] = fmaf(aa[i], bb[j], s[i][j]);
        }

        const float scale = 0.125f;
        if (kt == qt) {
            #pragma unroll
            for (int i = 0; i < 4; i++)
                #pragma unroll
                for (int j = 0; j < 4; j++)
                    s[i][j] = (n0 + j <= m0 + i) ? s[i][j] * scale : -1e30f;
        } else {
            #pragma unroll
            for (int i = 0; i < 4; i++)
                #pragma unroll
                for (int j = 0; j < 4; j++)
                    s[i][j] *= scale;
        }

        float p[4][4];
        #pragma unroll
        for (int i = 0; i < 4; i++) {
            float mx = fmaxf(fmaxf(s[i][0], s[i][1]), fmaxf(s[i][2], s[i][3]));
            #pragma unroll
            for (int o = 1; o < 16; o <<= 1)
                mx = fmaxf(mx, __shfl_xor_sync(0xffffffffu, mx, o));
            float nm = fmaxf(row_max[i], mx);
            float alpha = __expf(row_max[i] - nm);
            row_max[i] = nm;
            float rs = 0.f;
            #pragma unroll
            for (int j = 0; j < 4; j++) { p[i][j] = __expf(s[i][j] - nm); rs += p[i][j]; }
            #pragma unroll
            for (int o = 1; o < 16; o <<= 1)
                rs += __shfl_xor_sync(0xffffffffu, rs, o);
            row_sum[i] = row_sum[i] * alpha + rs;
            #pragma unroll
            for (int j = 0; j < 4; j++) o_acc[i][j] *= alpha;
        }

        __syncthreads();
        #pragma unroll
        for (int i = 0; i < 4; i++)
            #pragma unroll
            for (int j = 0; j < 4; j++)
                Ps[m0 + i][n0 + j] = p[i][j];
        __syncthreads();

        #pragma unroll 8
        for (int n = 0; n < 64; n++) {
            float4 vv = *(const float4*)&Vs[n][n0];
            float vb[4] = {vv.x, vv.y, vv.z, vv.w};
            #pragma unroll
            for (int i = 0; i < 4; i++) {
                float pv = Ps[m0 + i][n];
                #pragma unroll
                for (int j = 0; j < 4; j++)
                    o_acc[i][j] = fmaf(pv, vb[j], o_acc[i][j]);
            }
        }
    }

    #pragma unroll
    for (int i = 0; i < 4; i++) {
        float inv = 1.f / row_sum[i];
        int t = qt * 64 + m0 + i;
        float4 ov = make_float4(o_acc[i][0] * inv, o_acc[i][1] * inv,
                                o_acc[i][2] * inv, o_acc[i][3] * inv);
        *(float4*)(O + ((size_t)(b * T + t)) * (NH * HD) + h * HD + n0) = ov;
    }
}

// ---------------- SwiGLU elementwise ----------------
__global__ void silu_mul_kernel(float* __restrict__ g, const float* __restrict__ u) {
    int i = blockIdx.x * blockDim.x + threadIdx.x;
    float4 gv = ((const float4*)g)[i];
    float4 uv = ((const float4*)u)[i];
    gv.x = gv.x / (1.f + __expf(-gv.x)) * uv.x;
    gv.y = gv.y / (1.f + __expf(-gv.y)) * uv.y;
    gv.z = gv.z / (1.f + __expf(-gv.z)) * uv.z;
    gv.w = gv.w / (1.f + __expf(-gv.w)) * uv.w;
    ((float4*)g)[i] = gv;
}

// ---------------- launch ----------------
extern "C" void kernel_launch(void* const* d_in, const int* in_sizes, int n_in,
                              void* d_out, int out_size) {
    const float* hs   = (const float*)d_in[0];
    const float* cosp = (const float*)d_in[1];
    const float* sinp = (const float*)d_in[2];
    const int*   pos  = (const int*)  d_in[3];
    const float* n1w  = (const float*)d_in[5];
    const float* wq   = (const float*)d_in[6];
    const float* wk   = (const float*)d_in[7];
    const float* wv   = (const float*)d_in[8];
    const float* wo   = (const float*)d_in[9];
    const float* n2w  = (const float*)d_in[10];
    const float* wg   = (const float*)d_in[11];
    const float* wu   = (const float*)d_in[12];
    const float* wd   = (const float*)d_in[13];

    float *xn, *q, *k, *v, *attn, *h2, *xn2, *gg, *uu;
    cudaGetSymbolAddress((void**)&xn,   g_xn);
    cudaGetSymbolAddress((void**)&q,    g_q);
    cudaGetSymbolAddress((void**)&k,    g_k);
    cudaGetSymbolAddress((void**)&v,    g_v);
    cudaGetSymbolAddress((void**)&attn, g_attn);
    cudaGetSymbolAddress((void**)&h2,   g_h2);
    cudaGetSymbolAddress((void**)&xn2,  g_xn2);
    cudaGetSymbolAddress((void**)&gg,   g_g);
    cudaGetSymbolAddress((void**)&uu,   g_u);

    float* out_x = (float*)d_out;
    float* out_k = out_x + (size_t)M * H;
    float* out_v = out_k + (size_t)B * NKV * T * HD;

    cudaFuncSetAttribute(gemm_mma_kernel,
                         cudaFuncAttributeMaxDynamicSharedMemorySize, GEMM_DSMEM);

    // 1. RMSNorm 1
    rmsnorm_kernel<<<M, 256>>>(hs, n1w, xn);
    // 2. Q/K/V projections (3xTF32 mma.sync NT GEMMs)
    gemm_mma_kernel<<<dim3((NH  * HD) / 128, M / 128), 256, GEMM_DSMEM>>>(xn, wq, nullptr, q, NH * HD, H);
    gemm_mma_kernel<<<dim3((NKV * HD) / 128, M / 128), 256, GEMM_DSMEM>>>(xn, wk, nullptr, k, NKV * HD, H);
    gemm_mma_kernel<<<dim3((NKV * HD) / 128, M / 128), 256, GEMM_DSMEM>>>(xn, wv, nullptr, v, NKV * HD, H);
    // 3. RoPE + KV-cache writeout
    rope_q_kernel <<<(B * T * NH  * (HD / 2)) / 256, 256>>>(q, cosp, sinp, pos);
    rope_kv_kernel<<<(B * T * NKV * (HD / 2)) / 256, 256>>>(k, v, cosp, sinp, pos,
                                                            out_k, out_v);
    // 4. Attention
    attn_kernel<<<dim3(T / 64, NH, B), 256>>>(q, k, v, attn);
    // 5. O-projection + residual
    gemm_mma_kernel<<<dim3(H / 128, M / 128), 256, GEMM_DSMEM>>>(attn, wo, hs, h2, H, NH * HD);
    // 6. RMSNorm 2
    rmsnorm_kernel<<<M, 256>>>(h2, n2w, xn2);
    // 7. MLP gate/up
    gemm_mma_kernel<<<dim3(IM / 128, M / 128), 256, GEMM_DSMEM>>>(xn2, wg, nullptr, gg, IM, H);
    gemm_mma_kernel<<<dim3(IM / 128, M / 128), 256, GEMM_DSMEM>>>(xn2, wu, nullptr, uu, IM, H);
    // 8. SwiGLU
    silu_mul_kernel<<<((size_t)M * IM / 4) / 256, 256>>>(gg, uu);
    // 9. Down projection + residual -> x output
    gemm_mma_kernel<<<dim3(H / 128, M / 128), 256, GEMM_DSMEM>>>(gg, wd, h2, out_x, H, IM);
}